// round 1
// baseline (speedup 1.0000x reference)
#include <cuda_runtime.h>
#include <math.h>

#define TT 128
#define NN 1000
#define EE 16000
#define FF 397
#define HH 128
#define DD 8
#define G4 512   // 4*HH

// ---- static scratch (allocation-free rule: __device__ globals) ----
__device__ float g_Y [TT*NN*HH];   // GEMM output buffer (reused layer1/2)
__device__ float g_H1[TT*NN*HH];   // relu(gemm + agg) buffer (reused)
__device__ int   g_cnt  [TT*NN];
__device__ int   g_start[TT*NN];
__device__ int   g_cur  [TT*NN];
__device__ int   g_eidx [TT*EE];
__device__ float g_pool [TT*HH];
__device__ float g_Gx   [TT*G4];

// ---------------- CSR build ----------------
__global__ void zero_cnt_kernel() {
    int i = blockIdx.x*blockDim.x + threadIdx.x;
    if (i < TT*NN) g_cnt[i] = 0;
}

__global__ void hist_kernel(const int* __restrict__ ei) {
    int e = blockIdx.x*blockDim.x + threadIdx.x;
    int t = blockIdx.y;
    if (e < EE) {
        int dst = ei[t*2*EE + EE + e];
        atomicAdd(&g_cnt[t*NN + dst], 1);
    }
}

__global__ void scan_kernel() {   // one block per t, Hillis-Steele over 1024
    __shared__ int s[1024];
    int t = blockIdx.x, tid = threadIdx.x;
    int v0 = (tid < NN) ? g_cnt[t*NN + tid] : 0;
    s[tid] = v0;
    __syncthreads();
    for (int off = 1; off < 1024; off <<= 1) {
        int v = (tid >= off) ? s[tid - off] : 0;
        __syncthreads();
        s[tid] += v;
        __syncthreads();
    }
    if (tid < NN) {
        int st = s[tid] - v0;          // exclusive
        g_start[t*NN + tid] = st;
        g_cur  [t*NN + tid] = st;
    }
}

__global__ void fill_kernel(const int* __restrict__ ei) {
    int e = blockIdx.x*blockDim.x + threadIdx.x;
    int t = blockIdx.y;
    if (e < EE) {
        int src = ei[t*2*EE + e];
        int dst = ei[t*2*EE + EE + e];
        int pos = atomicAdd(&g_cur[t*NN + dst], 1);
        g_eidx[t*EE + pos] = src;
    }
}

// ---------------- GEMM: C[M x 128] = A[M x K] @ W^T + bias ----------------
// BM=64, BN=128, BK=16, 256 threads, 8x4 per-thread tile.
__global__ void __launch_bounds__(256) gemm_bias_kernel(
    const float* __restrict__ A, const float* __restrict__ W,
    const float* __restrict__ bias, float* __restrict__ C, int K)
{
    __shared__ float As[16][64];
    __shared__ float Bs[16][128];
    int tid = threadIdx.x;
    int m0  = blockIdx.x * 64;

    float acc[8][4];
    #pragma unroll
    for (int i = 0; i < 8; i++)
        #pragma unroll
        for (int j = 0; j < 4; j++) acc[i][j] = 0.f;

    int tm = (tid >> 5) << 3;      // warp id * 8 rows (broadcast reads)
    int tn = (tid & 31) << 2;      // lane * 4 cols
    int ar = tid >> 2, ak = (tid & 3) << 2;
    int wc = tid >> 1, wk = (tid & 1) << 3;
    const float* Arow = A + (long)(m0 + ar) * K;
    const float* Wrow = W + (long)wc * K;

    for (int k0 = 0; k0 < K; k0 += 16) {
        #pragma unroll
        for (int i = 0; i < 4; i++) {
            int k = k0 + ak + i;
            As[ak + i][ar] = (k < K) ? Arow[k] : 0.f;
        }
        #pragma unroll
        for (int i = 0; i < 8; i++) {
            int k = k0 + wk + i;
            Bs[wk + i][wc] = (k < K) ? Wrow[k] : 0.f;
        }
        __syncthreads();
        #pragma unroll
        for (int k = 0; k < 16; k++) {
            float a[8], b[4];
            *(float4*)&a[0] = *(const float4*)&As[k][tm];
            *(float4*)&a[4] = *(const float4*)&As[k][tm + 4];
            *(float4*)&b[0] = *(const float4*)&Bs[k][tn];
            #pragma unroll
            for (int i = 0; i < 8; i++)
                #pragma unroll
                for (int j = 0; j < 4; j++)
                    acc[i][j] += a[i] * b[j];
        }
        __syncthreads();
    }

    float4 bv = *(const float4*)&bias[tn];
    #pragma unroll
    for (int i = 0; i < 8; i++) {
        float4 v = make_float4(acc[i][0] + bv.x, acc[i][1] + bv.y,
                               acc[i][2] + bv.z, acc[i][3] + bv.w);
        *(float4*)&C[(long)(m0 + tm + i) * HH + tn] = v;
    }
}

// -------- gather + relu (fuses GIN self-term + neighbor sum + ReLU) --------
// warp per dst node, lane l owns features [4l,4l+4)
__global__ void __launch_bounds__(256) gather_relu_kernel(
    const float* __restrict__ Y, float* __restrict__ Out)
{
    int wid  = threadIdx.x >> 5, lane = threadIdx.x & 31;
    int dst  = blockIdx.x * 8 + wid;
    int t    = blockIdx.y;
    if (dst >= NN) return;
    const float* base = Y + t * NN * HH;
    float4 acc = *(const float4*)&base[dst * HH + lane * 4];   // self term (has bias)
    int s   = g_start[t*NN + dst];
    int cnt = g_cnt  [t*NN + dst];
    const int* ep = g_eidx + t*EE + s;
    int i = 0;
    for (; i + 4 <= cnt; i += 4) {
        int s0 = ep[i], s1 = ep[i+1], s2 = ep[i+2], s3 = ep[i+3];
        float4 v0 = *(const float4*)&base[s0*HH + lane*4];
        float4 v1 = *(const float4*)&base[s1*HH + lane*4];
        float4 v2 = *(const float4*)&base[s2*HH + lane*4];
        float4 v3 = *(const float4*)&base[s3*HH + lane*4];
        acc.x += v0.x + v1.x + v2.x + v3.x;
        acc.y += v0.y + v1.y + v2.y + v3.y;
        acc.z += v0.z + v1.z + v2.z + v3.z;
        acc.w += v0.w + v1.w + v2.w + v3.w;
    }
    for (; i < cnt; i++) {
        int s0 = ep[i];
        float4 v = *(const float4*)&base[s0*HH + lane*4];
        acc.x += v.x; acc.y += v.y; acc.z += v.z; acc.w += v.w;
    }
    acc.x = fmaxf(acc.x, 0.f); acc.y = fmaxf(acc.y, 0.f);
    acc.z = fmaxf(acc.z, 0.f); acc.w = fmaxf(acc.w, 0.f);
    *(float4*)&Out[(t*NN + dst)*HH + lane*4] = acc;
}

// ---------------- mean pool over N ----------------
__global__ void pool_kernel(const float* __restrict__ Hin) {
    int t = blockIdx.x, c = threadIdx.x;   // 128 threads
    const float* p = Hin + t*NN*HH + c;
    float s0 = 0, s1 = 0, s2 = 0, s3 = 0;
    for (int n = 0; n < NN; n += 4) {
        s0 += p[(n+0)*HH];
        s1 += p[(n+1)*HH];
        s2 += p[(n+2)*HH];
        s3 += p[(n+3)*HH];
    }
    g_pool[t*HH + c] = (s0 + s1 + s2 + s3) * (1.f / NN);
}

// -------- input-side LSTM gates: Gx[t,j] = b_ih+b_hh + seq_t . w_ih[j] -----
__global__ void __launch_bounds__(512) gx_kernel(
    const int* __restrict__ dok, const float* __restrict__ emb,
    const float* __restrict__ w_ih, const float* __restrict__ b_ih,
    const float* __restrict__ b_hh)
{
    __shared__ float sseq[HH + DD];
    int t = blockIdx.x, j = threadIdx.x;
    if (j < HH)            sseq[j] = g_pool[t*HH + j];
    else if (j < HH + DD)  sseq[j] = emb[dok[t]*DD + (j - HH)];
    __syncthreads();
    const float* wr = w_ih + j * (HH + DD);
    float a0 = b_ih[j] + b_hh[j], a1 = 0.f;
    #pragma unroll
    for (int k = 0; k < HH + DD; k += 2) {
        a0 += wr[k]   * sseq[k];
        a1 += wr[k+1] * sseq[k+1];
    }
    g_Gx[t*G4 + j] = a0 + a1;
}

// ---------------- sequential LSTM + final FC, single persistent CTA -------
// Each of 512 threads owns one gate row of w_hh: cols 0..63 in registers,
// cols 64..127 in padded smem (pitch 68 -> conflict-free LDS.128).
#define SPITCH 68
__global__ void __launch_bounds__(512) lstm_kernel(
    const float* __restrict__ w_hh, const float* __restrict__ w_fc,
    const float* __restrict__ b_fc, float* __restrict__ out)
{
    extern __shared__ float sm[];
    float* sW   = sm;                  // 512*68
    float* sh   = sW + G4*SPITCH;      // 128
    float* sg   = sh + HH;             // 512
    float* sred = sg + G4;             // 32

    int tid = threadIdx.x;

    float4 rw[16];
    const float4* wg4 = (const float4*)(w_hh + tid * HH);
    #pragma unroll
    for (int i = 0; i < 16; i++) rw[i] = wg4[i];          // cols 0..63

    for (int i = tid; i < G4 * 64; i += 512) {            // cols 64..127
        int r = i >> 6, c = i & 63;
        sW[r*SPITCH + c] = w_hh[r*HH + 64 + c];
    }
    if (tid < HH) sh[tid] = 0.f;
    float c_state = 0.f;
    float wfc = (tid < HH) ? w_fc[tid] : 0.f;
    float bfc = b_fc[0];
    __syncthreads();

    const float4* wr4 = (const float4*)(sW + tid * SPITCH);  // 272B rows, 16B aligned

    for (int t = 0; t < TT; t++) {
        const float4* sh4 = (const float4*)sh;
        float a0 = 0, a1 = 0, a2 = 0, a3 = 0;
        #pragma unroll
        for (int k = 0; k < 16; k++) {
            float4 hv = sh4[k]; float4 w = rw[k];
            a0 += w.x*hv.x; a1 += w.y*hv.y; a2 += w.z*hv.z; a3 += w.w*hv.w;
        }
        #pragma unroll
        for (int k = 0; k < 16; k++) {
            float4 hv = sh4[16 + k]; float4 w = wr4[k];
            a0 += w.x*hv.x; a1 += w.y*hv.y; a2 += w.z*hv.z; a3 += w.w*hv.w;
        }
        sg[tid] = g_Gx[t*G4 + tid] + (a0 + a1) + (a2 + a3);
        __syncthreads();
        if (tid < HH) {
            float ig = 1.f / (1.f + expf(-sg[tid]));
            float fg = 1.f / (1.f + expf(-sg[tid + HH]));
            float gg = tanhf(sg[tid + 2*HH]);
            float og = 1.f / (1.f + expf(-sg[tid + 3*HH]));
            c_state = fg * c_state + ig * gg;
            float h = og * tanhf(c_state);
            sh[tid] = h;
            float p = h * wfc;
            #pragma unroll
            for (int o = 16; o > 0; o >>= 1) p += __shfl_down_sync(0xffffffffu, p, o);
            if ((tid & 31) == 0) sred[tid >> 5] = p;
        }
        __syncthreads();
        if (tid == 0) out[t] = sred[0] + sred[1] + sred[2] + sred[3] + bfc;
    }
}

// ---------------- launch ----------------
extern "C" void kernel_launch(void* const* d_in, const int* in_sizes, int n_in,
                              void* d_out, int out_size)
{
    const float* x    = (const float*)d_in[0];
    const int*   ei   = (const int*)  d_in[1];
    const int*   dok  = (const int*)  d_in[2];
    const float* w1   = (const float*)d_in[3];
    const float* b1   = (const float*)d_in[4];
    const float* w2   = (const float*)d_in[5];
    const float* b2   = (const float*)d_in[6];
    const float* emb  = (const float*)d_in[7];
    const float* w_ih = (const float*)d_in[8];
    const float* w_hh = (const float*)d_in[9];
    const float* b_ih = (const float*)d_in[10];
    const float* b_hh = (const float*)d_in[11];
    const float* w_fc = (const float*)d_in[12];
    const float* b_fc = (const float*)d_in[13];
    float* out = (float*)d_out;

    float *pY, *pH1;
    cudaGetSymbolAddress((void**)&pY,  g_Y);
    cudaGetSymbolAddress((void**)&pH1, g_H1);

    // CSR build (shared by both GIN layers)
    zero_cnt_kernel<<<(TT*NN + 255)/256, 256>>>();
    dim3 eg((EE + 255)/256, TT);
    hist_kernel<<<eg, 256>>>(ei);
    scan_kernel<<<TT, 1024>>>();
    fill_kernel<<<eg, 256>>>(ei);

    // GIN layer 1: y = x@w1^T + b1 ; h1 = relu(y[dst] + sum y[src])
    gemm_bias_kernel<<<TT*NN/64, 256>>>(x, w1, b1, pY, FF);
    dim3 gg((NN + 7)/8, TT);
    gather_relu_kernel<<<gg, 256>>>(pY, pH1);

    // GIN layer 2
    gemm_bias_kernel<<<TT*NN/64, 256>>>(pH1, w2, b2, pY, HH);
    gather_relu_kernel<<<gg, 256>>>(pY, pH1);

    // pool, LSTM input gates, sequential LSTM + FC
    pool_kernel<<<TT, HH>>>(pH1);
    gx_kernel<<<TT, 512>>>(dok, emb, w_ih, b_ih, b_hh);

    size_t lsm = (size_t)(G4*SPITCH + HH + G4 + 32) * sizeof(float);
    cudaFuncSetAttribute(lstm_kernel, cudaFuncAttributeMaxDynamicSharedMemorySize, (int)lsm);
    lstm_kernel<<<1, 512, lsm>>>(w_hh, w_fc, b_fc, out);
}